// round 2
// baseline (speedup 1.0000x reference)
#include <cuda_runtime.h>
#include <cuda_bf16.h>

// BinaryTimedPSP: out[t] = clip(sliding causal window-sum(x, duration), 0, 1)
// Spikes are binary (0/1), so out[t] = 1 iff any spike in [t-duration+1, t].
// Implemented as a per-column "age since last spike" scan.
//
// Layout: x[T, B, N] fp32, contiguous N fastest. ROW = B*N. Consecutive
// threads cover consecutive n (float4) -> fully coalesced 128B lines.
// T is split into SEG segments per column for parallelism; each segment
// re-reads a (duration-1) halo to seed the age counter.

#define TDIM 2048
#define SEG 8
#define SEG_LEN (TDIM / SEG)
#define BLOCK 128

__global__ __launch_bounds__(BLOCK) void psp_scan_kernel(
    const float4* __restrict__ x,
    float4* __restrict__ out,
    const int* __restrict__ durp,
    int row4)   // ROW/4 = number of float4 per timestep
{
    const int c = blockIdx.x * BLOCK + threadIdx.x;   // column group (float4) index
    if (c >= row4) return;
    const int s = blockIdx.y;                          // time segment

    int d = 100;
    if (durp) {
        int dv = *durp;                    // device scalar, L2-cached
        if (dv > 0 && dv <= (TDIM * 16)) d = dv;   // sanity guard vs dtype surprises
    }

    const int t0 = s * SEG_LEN;
    int th = t0 - (d - 1);
    if (th < 0) th = 0;

    // age since last spike per lane component; big = "never"
    int ax = 1 << 28, ay = 1 << 28, az = 1 << 28, aw = 1 << 28;

    // Halo: seed the counters (no stores)
    #pragma unroll 4
    for (int t = th; t < t0; ++t) {
        float4 v = x[t * row4 + c];
        ax = (v.x != 0.0f) ? 0 : ax + 1;
        ay = (v.y != 0.0f) ? 0 : ay + 1;
        az = (v.z != 0.0f) ? 0 : az + 1;
        aw = (v.w != 0.0f) ? 0 : aw + 1;
    }

    // Main segment: scan + store
    #pragma unroll 8
    for (int t = t0; t < t0 + SEG_LEN; ++t) {
        float4 v = x[t * row4 + c];
        ax = (v.x != 0.0f) ? 0 : ax + 1;
        ay = (v.y != 0.0f) ? 0 : ay + 1;
        az = (v.z != 0.0f) ? 0 : az + 1;
        aw = (v.w != 0.0f) ? 0 : aw + 1;
        float4 o;
        o.x = (ax < d) ? 1.0f : 0.0f;
        o.y = (ay < d) ? 1.0f : 0.0f;
        o.z = (az < d) ? 1.0f : 0.0f;
        o.w = (aw < d) ? 1.0f : 0.0f;
        out[t * row4 + c] = o;
    }
}

extern "C" void kernel_launch(void* const* d_in, const int* in_sizes, int n_in,
                              void* d_out, int out_size)
{
    const float* x = (const float*)d_in[0];
    const int* durp = (n_in > 1) ? (const int*)d_in[1] : nullptr;
    float* out = (float*)d_out;

    const int total = in_sizes[0];          // T * B * N
    const int row = total / TDIM;           // B * N (contiguous per timestep)
    const int row4 = row / 4;

    dim3 grid((row4 + BLOCK - 1) / BLOCK, SEG);
    psp_scan_kernel<<<grid, BLOCK>>>((const float4*)x, (float4*)out, durp, row4);
}